// round 16
// baseline (speedup 1.0000x reference)
#include <cuda_runtime.h>
#include <cuda_bf16.h>

#define NN 50000
#define IC 512
#define OC 128
#define NE 1600000
#define MAXDEG 192   // P(Poisson(32) > 192) ~ 0; guarded anyway

typedef unsigned long long ull;
typedef unsigned int uint;

// ---------------------------------------------------------------------------
// Scratch (static __device__ — zero-initialized at load; no allocation)
__device__ int   g_cnt[NN];                 // in-degree; re-zeroed by k_gather
__device__ int   g_csrc2[(size_t)NN * MAXDEG];  // bucketed sources per dst
__device__ float g_dis[NN];
__device__ __nv_bfloat16 g_y[(size_t)NN * OC];  // x @ W_enc (UNSCALED, bf16)
__device__ float g_h[(size_t)(NN + 32) * OC];   // relu(dis*(gather) + b), padded

// tf32 B fragments, lane-contiguous:
__device__ uint2 g_BpE[64 * 16 * 32];
__device__ uint2 g_BpD[16 * 64 * 32];

__device__ __forceinline__ uint tf32c(float f) {
    uint u;
    asm("cvt.rna.tf32.f32 %0, %1;" : "=r"(u) : "f"(f));
    return u;
}
__device__ __forceinline__ void mma_tf32(float* c, const uint* a, uint2 b) {
    asm volatile(
        "mma.sync.aligned.m16n8k8.row.col.f32.tf32.tf32.f32 "
        "{%0,%1,%2,%3}, {%4,%5,%6,%7}, {%8,%9}, {%0,%1,%2,%3};"
        : "+f"(c[0]), "+f"(c[1]), "+f"(c[2]), "+f"(c[3])
        : "r"(a[0]), "r"(a[1]), "r"(a[2]), "r"(a[3]), "r"(b.x), "r"(b.y));
}

// ---------------------------------------------------------------------------
// K1: one-pass bucket scatter. g_cnt is zero on entry (static init on first
// call; re-zeroed by k_gather every call). 4 edges per thread, int4 loads.
__global__ __launch_bounds__(256) void k_scatter2(const int* __restrict__ ei) {
    int i = blockIdx.x * blockDim.x + threadIdx.x;   // 0 .. NE/4-1
    if (i >= NE / 4) return;
    const int4* e4 = (const int4*)ei;
    int4 s = e4[i];
    int4 d = e4[NE / 4 + i];
    int p;
    p = atomicAdd(&g_cnt[d.x], 1); if (p < MAXDEG) g_csrc2[(size_t)d.x * MAXDEG + p] = s.x;
    p = atomicAdd(&g_cnt[d.y], 1); if (p < MAXDEG) g_csrc2[(size_t)d.y * MAXDEG + p] = s.y;
    p = atomicAdd(&g_cnt[d.z], 1); if (p < MAXDEG) g_csrc2[(size_t)d.z * MAXDEG + p] = s.z;
    p = atomicAdd(&g_cnt[d.w], 1); if (p < MAXDEG) g_csrc2[(size_t)d.w * MAXDEG + p] = s.w;
}

// K2: dis = rsqrt(cnt + 1)
__global__ __launch_bounds__(256) void k_dis() {
    int i = blockIdx.x * blockDim.x + threadIdx.x;
    if (i < NN) g_dis[i] = rsqrtf((float)(g_cnt[i] + 1));
}

// K_prep: tf32 B fragments for both GEMMs
__global__ void k_prep(const float* __restrict__ We, const float* __restrict__ Wd) {
    int i = blockIdx.x * blockDim.x + threadIdx.x;
    if (i < 64 * 16 * 32) {  // enc fragments
        int kt = i >> 9, gnt = (i >> 5) & 15, lane = i & 31;
        int k = kt * 8 + (lane & 3);
        int n = gnt * 8 + (lane >> 2);
        uint2 b;
        b.x = tf32c(We[k * OC + n]);
        b.y = tf32c(We[(k + 4) * OC + n]);
        g_BpE[i] = b;
    }
    if (i < 16 * 64 * 32) {  // dec fragments
        int kt = i >> 11, gnt = (i >> 5) & 63, lane = i & 31;
        int k = kt * 8 + (lane & 3);
        int n = gnt * 8 + (lane >> 2);
        uint2 b;
        b.x = tf32c(Wd[k * IC + n]);
        b.y = tf32c(Wd[(k + 4) * IC + n]);
        g_BpD[i] = b;
    }
}

// ---------------------------------------------------------------------------
// K4: y = x @ W_enc (UNSCALED, bf16 out) via tf32 mma m16n8k8.
__global__ __launch_bounds__(256) void k_gemm1(const float* __restrict__ x) {
    __shared__ __align__(16) float xs[32 * 132];  // row stride 132
    const int tid = threadIdx.x, warp = tid >> 5, lane = tid & 31;
    const int q = lane >> 2, c2 = lane & 3;
    const int r0blk = blockIdx.x * 32;

    float c[2][2][4];
#pragma unroll
    for (int t = 0; t < 2; t++)
#pragma unroll
        for (int nt = 0; nt < 2; nt++)
#pragma unroll
            for (int j = 0; j < 4; j++) c[t][nt][j] = 0.f;

#pragma unroll 1
    for (int ch = 0; ch < 4; ch++) {
        __syncthreads();
#pragma unroll
        for (int it = 0; it < 4; it++) {
            int idx = it * 256 + tid;
            int row = idx >> 5, c4 = idx & 31;
            int grow = min(r0blk + row, NN - 1);
            float4 v = *(const float4*)(x + (size_t)grow * IC + ch * 128 + c4 * 4);
            *(float4*)&xs[row * 132 + c4 * 4] = v;
        }
        __syncthreads();

#pragma unroll
        for (int kt2 = 0; kt2 < 16; kt2++) {
            int ktg = ch * 16 + kt2;
            uint a[2][4];
#pragma unroll
            for (int t = 0; t < 2; t++) {
                int r = t * 16 + q;
                a[t][0] = tf32c(xs[r * 132 + kt2 * 8 + c2]);
                a[t][1] = tf32c(xs[(r + 8) * 132 + kt2 * 8 + c2]);
                a[t][2] = tf32c(xs[r * 132 + kt2 * 8 + c2 + 4]);
                a[t][3] = tf32c(xs[(r + 8) * 132 + kt2 * 8 + c2 + 4]);
            }
#pragma unroll
            for (int nt = 0; nt < 2; nt++) {
                uint2 b = g_BpE[(ktg * 16 + warp * 2 + nt) * 32 + lane];
#pragma unroll
                for (int t = 0; t < 2; t++) mma_tf32(c[t][nt], a[t], b);
            }
        }
    }

#pragma unroll
    for (int t = 0; t < 2; t++) {
        int rowL = r0blk + t * 16 + q;
        int rowH = rowL + 8;
#pragma unroll
        for (int nt = 0; nt < 2; nt++) {
            int col = warp * 16 + nt * 8 + 2 * c2;
            if (rowL < NN)
                *(__nv_bfloat162*)&g_y[(size_t)rowL * OC + col] =
                    __float22bfloat162_rn(make_float2(c[t][nt][0], c[t][nt][1]));
            if (rowH < NN)
                *(__nv_bfloat162*)&g_y[(size_t)rowH * OC + col] =
                    __float22bfloat162_rn(make_float2(c[t][nt][2], c[t][nt][3]));
        }
    }
}

// ---------------------------------------------------------------------------
// K5: gather + epilogue, one warp per node, 8-wide pipeline. Also re-zeros
// g_cnt[n] for the next call (read-then-reset; deterministic across replays).
__device__ __forceinline__ float4 ld_y4(const uint2* y2, int row, int lane) {
    uint2 u = y2[(size_t)row * 32 + lane];
    float2 lo = __bfloat1622float2(*(__nv_bfloat162*)&u.x);
    float2 hi = __bfloat1622float2(*(__nv_bfloat162*)&u.y);
    return make_float4(lo.x, lo.y, hi.x, hi.y);
}

__global__ __launch_bounds__(256) void k_gather(const float* __restrict__ b) {
    const int w = blockIdx.x * 8 + (threadIdx.x >> 5);
    if (w >= NN) return;
    const int lane = threadIdx.x & 31;
    const int n = w;

    const uint2* __restrict__ y2 = (const uint2*)g_y;
    const int* __restrict__ row = g_csrc2 + (size_t)n * MAXDEG;

    int cnt = g_cnt[n];
    int end = min(cnt, MAXDEG);
    float dn = g_dis[n];

    float4 a = ld_y4(y2, n, lane);  // self loop
    a.x *= dn; a.y *= dn; a.z *= dn; a.w *= dn;

    int e = 0;
    for (; e + 8 <= end; e += 8) {
        int s[8];
#pragma unroll
        for (int j = 0; j < 8; j++) s[j] = row[e + j];
        float4 v[8];
#pragma unroll
        for (int j = 0; j < 8; j++) v[j] = ld_y4(y2, s[j], lane);
        float ds[8];
#pragma unroll
        for (int j = 0; j < 8; j++) ds[j] = g_dis[s[j]];
#pragma unroll
        for (int j = 0; j < 8; j++) {
            a.x = fmaf(v[j].x, ds[j], a.x);
            a.y = fmaf(v[j].y, ds[j], a.y);
            a.z = fmaf(v[j].z, ds[j], a.z);
            a.w = fmaf(v[j].w, ds[j], a.w);
        }
    }
    for (; e < end; e++) {
        int s = row[e];
        float ds = g_dis[s];
        float4 v = ld_y4(y2, s, lane);
        a.x = fmaf(v.x, ds, a.x); a.y = fmaf(v.y, ds, a.y);
        a.z = fmaf(v.z, ds, a.z); a.w = fmaf(v.w, ds, a.w);
    }
    const float4 b4 = ((const float4*)b)[lane];
    float4 h;
    h.x = fmaxf(fmaf(dn, a.x, b4.x), 0.f);
    h.y = fmaxf(fmaf(dn, a.y, b4.y), 0.f);
    h.z = fmaxf(fmaf(dn, a.z, b4.z), 0.f);
    h.w = fmaxf(fmaf(dn, a.w, b4.w), 0.f);
    ((float4*)g_h)[(size_t)n * 32 + lane] = h;

    if (lane == 0) g_cnt[n] = 0;  // ready for next call
}

// ---------------------------------------------------------------------------
// K6: decode GEMM via tf32 mma.sync m16n8k8 + softmax.
__global__ __launch_bounds__(256) void k_dec(float* __restrict__ out) {
    __shared__ __align__(16) float hs[32 * 132];
    __shared__ float red_m[2][16][8];
    __shared__ float red_s[2][16][8];
    const int tid = threadIdx.x, warp = tid >> 5, lane = tid & 31;
    const int q = lane >> 2, c2 = lane & 3;
    const int n0 = blockIdx.x * 32;

#pragma unroll
    for (int it = 0; it < 4; it++) {
        int idx = it * 256 + tid;
        int row = idx >> 5, c4 = idx & 31;
        float4 v = *(const float4*)(g_h + (size_t)(n0 + row) * OC + c4 * 4);
        *(float4*)&hs[row * 132 + c4 * 4] = v;
    }
    __syncthreads();

    float c[2][8][4];
#pragma unroll
    for (int t = 0; t < 2; t++)
#pragma unroll
        for (int nt = 0; nt < 8; nt++)
#pragma unroll
            for (int j = 0; j < 4; j++) c[t][nt][j] = 0.f;

    for (int kt = 0; kt < 16; kt++) {
        uint a[2][4];
#pragma unroll
        for (int t = 0; t < 2; t++) {
            int r0 = t * 16 + q;
            a[t][0] = tf32c(hs[r0 * 132 + kt * 8 + c2]);
            a[t][1] = tf32c(hs[(r0 + 8) * 132 + kt * 8 + c2]);
            a[t][2] = tf32c(hs[r0 * 132 + kt * 8 + c2 + 4]);
            a[t][3] = tf32c(hs[(r0 + 8) * 132 + kt * 8 + c2 + 4]);
        }
#pragma unroll
        for (int nt = 0; nt < 8; nt++) {
            uint2 b = g_BpD[(kt * 64 + warp * 8 + nt) * 32 + lane];
#pragma unroll
            for (int t = 0; t < 2; t++) mma_tf32(c[t][nt], a[t], b);
        }
    }

    // --- softmax over 512 cols per row ---
#pragma unroll
    for (int t = 0; t < 2; t++) {
        float mL = -1e30f, mH = -1e30f;
#pragma unroll
        for (int nt = 0; nt < 8; nt++) {
            mL = fmaxf(mL, fmaxf(c[t][nt][0], c[t][nt][1]));
            mH = fmaxf(mH, fmaxf(c[t][nt][2], c[t][nt][3]));
        }
        mL = fmaxf(mL, __shfl_xor_sync(0xffffffffu, mL, 1));
        mL = fmaxf(mL, __shfl_xor_sync(0xffffffffu, mL, 2));
        mH = fmaxf(mH, __shfl_xor_sync(0xffffffffu, mH, 1));
        mH = fmaxf(mH, __shfl_xor_sync(0xffffffffu, mH, 2));
        if (c2 == 0) {
            red_m[t][q][warp] = mL;
            red_m[t][q + 8][warp] = mH;
        }
    }
    __syncthreads();

    float inv[2][2];
#pragma unroll
    for (int t = 0; t < 2; t++) {
        float rmL = red_m[t][q][0], rmH = red_m[t][q + 8][0];
#pragma unroll
        for (int w2 = 1; w2 < 8; w2++) {
            rmL = fmaxf(rmL, red_m[t][q][w2]);
            rmH = fmaxf(rmH, red_m[t][q + 8][w2]);
        }
        float sL = 0.f, sH = 0.f;
#pragma unroll
        for (int nt = 0; nt < 8; nt++) {
            c[t][nt][0] = __expf(c[t][nt][0] - rmL);
            c[t][nt][1] = __expf(c[t][nt][1] - rmL);
            c[t][nt][2] = __expf(c[t][nt][2] - rmH);
            c[t][nt][3] = __expf(c[t][nt][3] - rmH);
            sL += c[t][nt][0] + c[t][nt][1];
            sH += c[t][nt][2] + c[t][nt][3];
        }
        sL += __shfl_xor_sync(0xffffffffu, sL, 1);
        sL += __shfl_xor_sync(0xffffffffu, sL, 2);
        sH += __shfl_xor_sync(0xffffffffu, sH, 1);
        sH += __shfl_xor_sync(0xffffffffu, sH, 2);
        if (c2 == 0) {
            red_s[t][q][warp] = sL;
            red_s[t][q + 8][warp] = sH;
        }
    }
    __syncthreads();

#pragma unroll
    for (int t = 0; t < 2; t++) {
        float sL = 0.f, sH = 0.f;
#pragma unroll
        for (int w2 = 0; w2 < 8; w2++) {
            sL += red_s[t][q][w2];
            sH += red_s[t][q + 8][w2];
        }
        inv[t][0] = 1.f / sL;
        inv[t][1] = 1.f / sH;
    }

#pragma unroll
    for (int t = 0; t < 2; t++) {
        int rowL = n0 + t * 16 + q;
        int rowH = rowL + 8;
#pragma unroll
        for (int nt = 0; nt < 8; nt++) {
            int col = warp * 64 + nt * 8 + 2 * c2;
            if (rowL < NN) {
                float2 v = make_float2(c[t][nt][0] * inv[t][0],
                                       c[t][nt][1] * inv[t][0]);
                *(float2*)&out[(size_t)rowL * IC + col] = v;
            }
            if (rowH < NN) {
                float2 v = make_float2(c[t][nt][2] * inv[t][1],
                                       c[t][nt][3] * inv[t][1]);
                *(float2*)&out[(size_t)rowH * IC + col] = v;
            }
        }
    }
}

// ---------------------------------------------------------------------------
extern "C" void kernel_launch(void* const* d_in, const int* in_sizes, int n_in,
                              void* d_out, int out_size) {
    const float* x    = (const float*)d_in[0];
    const int*   ei   = (const int*)d_in[1];
    const float* Wenc = (const float*)d_in[2];
    const float* benc = (const float*)d_in[3];
    const float* Wdec = (const float*)d_in[4];
    float*       out  = (float*)d_out;

    // Streams/events created once on first (non-capture) call; reused.
    static cudaStream_t sB = nullptr;
    static cudaEvent_t evF = nullptr, evJ = nullptr;
    if (sB == nullptr) {
        cudaStreamCreateWithFlags(&sB, cudaStreamNonBlocking);
        cudaEventCreateWithFlags(&evF, cudaEventDisableTiming);
        cudaEventCreateWithFlags(&evJ, cudaEventDisableTiming);
    }

    // fork: stream B builds buckets while the main stream runs the encode GEMM
    cudaEventRecord(evF, 0);
    cudaStreamWaitEvent(sB, evF, 0);

    k_scatter2<<<(NE / 4 + 255) / 256, 256, 0, sB>>>(ei);
    k_dis<<<(NN + 255) / 256, 256, 0, sB>>>();

    k_prep<<<128, 256>>>(Wenc, Wdec);
    k_gemm1<<<(NN + 31) / 32, 256>>>(x);

    // join
    cudaEventRecord(evJ, sB);
    cudaStreamWaitEvent(0, evJ, 0);

    k_gather<<<(NN + 7) / 8, 256>>>(benc);
    k_dec<<<(NN + 31) / 32, 256>>>(out);
}

// round 17
// speedup vs baseline: 1.0245x; 1.0245x over previous
#include <cuda_runtime.h>
#include <cuda_bf16.h>

#define NN 50000
#define IC 512
#define OC 128
#define NE 1600000
#define NB 196   // scan blocks: 196*256 = 50176 >= NN

typedef unsigned long long ull;
typedef unsigned int uint;

// ---------------------------------------------------------------------------
// Scratch (static __device__ — zero-initialized at load; no allocation)
__device__ int   g_deg[NN];       // zero on entry; re-zeroed by k_off
__device__ int   g_off[NN + 1];   // CSR row offsets (by dst)
__device__ int   g_cur[NN];       // scatter cursors
__device__ int   g_csrc[NE];      // CSR column = src node per edge
__device__ float g_dis[NN];
__device__ int   g_bsum[NB];      // per-block degree sums
__device__ __nv_bfloat16 g_y[(size_t)NN * OC];  // x @ W_enc (UNSCALED, bf16)
__device__ float g_h[(size_t)(NN + 32) * OC];   // relu(dis*(gather) + b), padded

// tf32 B fragments, lane-contiguous:
__device__ uint2 g_BpE[64 * 16 * 32];
__device__ uint2 g_BpD[16 * 64 * 32];

__device__ __forceinline__ uint tf32c(float f) {
    uint u;
    asm("cvt.rna.tf32.f32 %0, %1;" : "=r"(u) : "f"(f));
    return u;
}
__device__ __forceinline__ void mma_tf32(float* c, const uint* a, uint2 b) {
    asm volatile(
        "mma.sync.aligned.m16n8k8.row.col.f32.tf32.tf32.f32 "
        "{%0,%1,%2,%3}, {%4,%5,%6,%7}, {%8,%9}, {%0,%1,%2,%3};"
        : "+f"(c[0]), "+f"(c[1]), "+f"(c[2]), "+f"(c[3])
        : "r"(a[0]), "r"(a[1]), "r"(a[2]), "r"(a[3]), "r"(b.x), "r"(b.y));
}

// ---------------------------------------------------------------------------
// K1: dst-degree histogram (g_deg zero on entry; re-zeroed by k_off each call)
__global__ void k_deg(const int* __restrict__ ei) {
    int i = blockIdx.x * blockDim.x + threadIdx.x;
    if (i < NE) atomicAdd(&g_deg[ei[NE + i]], 1);
}

// Scan stage 1: per-block sums of 256 degrees
__global__ __launch_bounds__(256) void k_bsum() {
    __shared__ int ss[8];
    int i = blockIdx.x * 256 + threadIdx.x;
    int v = (i < NN) ? g_deg[i] : 0;
#pragma unroll
    for (int o = 16; o; o >>= 1) v += __shfl_xor_sync(0xffffffffu, v, o);
    if ((threadIdx.x & 31) == 0) ss[threadIdx.x >> 5] = v;
    __syncthreads();
    if (threadIdx.x == 0) {
        int s = 0;
#pragma unroll
        for (int w = 0; w < 8; w++) s += ss[w];
        g_bsum[blockIdx.x] = s;
    }
}

// Scan stage 2 (fused): per-block reduce of bsum below bid + per-block scan
// of degrees -> off/cur/dis. Re-zeros g_deg for the next call.
__global__ __launch_bounds__(256) void k_off() {
    __shared__ int sc[256];
    __shared__ int sbase[8];
    const int t = threadIdx.x;
    const int bid = blockIdx.x;
    const int i = bid * 256 + t;

    int v = (t < bid && t < NB) ? g_bsum[t] : 0;
#pragma unroll
    for (int o = 16; o; o >>= 1) v += __shfl_xor_sync(0xffffffffu, v, o);
    if ((t & 31) == 0) sbase[t >> 5] = v;
    __syncthreads();
    int gbase = 0;
#pragma unroll
    for (int w = 0; w < 8; w++) gbase += sbase[w];

    int d = (i < NN) ? g_deg[i] : 0;
    sc[t] = d;
    __syncthreads();
    for (int off = 1; off < 256; off <<= 1) {
        int u = (t >= off) ? sc[t - off] : 0;
        __syncthreads();
        sc[t] += u;
        __syncthreads();
    }
    if (i < NN) {
        int base = gbase + sc[t] - d;  // exclusive
        g_off[i] = base;
        g_cur[i] = base;
        g_dis[i] = rsqrtf((float)(d + 1));
        g_deg[i] = 0;
        if (i == NN - 1) g_off[NN] = base + d;
    }
}

// K3: scatter edges into CSR (order within a row irrelevant for a sum)
__global__ void k_scatter(const int* __restrict__ ei) {
    int i = blockIdx.x * blockDim.x + threadIdx.x;
    if (i >= NE) return;
    int s = ei[i];
    int d = ei[NE + i];
    int p = atomicAdd(&g_cur[d], 1);
    g_csrc[p] = s;
}

// K_prep: tf32 B fragments for both GEMMs
__global__ void k_prep(const float* __restrict__ We, const float* __restrict__ Wd) {
    int i = blockIdx.x * blockDim.x + threadIdx.x;
    if (i < 64 * 16 * 32) {  // enc fragments
        int kt = i >> 9, gnt = (i >> 5) & 15, lane = i & 31;
        int k = kt * 8 + (lane & 3);
        int n = gnt * 8 + (lane >> 2);
        uint2 b;
        b.x = tf32c(We[k * OC + n]);
        b.y = tf32c(We[(k + 4) * OC + n]);
        g_BpE[i] = b;
    }
    if (i < 16 * 64 * 32) {  // dec fragments
        int kt = i >> 11, gnt = (i >> 5) & 63, lane = i & 31;
        int k = kt * 8 + (lane & 3);
        int n = gnt * 8 + (lane >> 2);
        uint2 b;
        b.x = tf32c(Wd[k * IC + n]);
        b.y = tf32c(Wd[(k + 4) * IC + n]);
        g_BpD[i] = b;
    }
}

// ---------------------------------------------------------------------------
// K4: y = x @ W_enc (UNSCALED, bf16 out) via tf32 mma m16n8k8.
// A staged in smem ALREADY tf32-converted (uint) — no cvt in the mainloop.
__global__ __launch_bounds__(256) void k_gemm1(const float* __restrict__ x) {
    __shared__ __align__(16) uint xs[32 * 132];  // tf32 bits, row stride 132
    const int tid = threadIdx.x, warp = tid >> 5, lane = tid & 31;
    const int q = lane >> 2, c2 = lane & 3;
    const int r0blk = blockIdx.x * 32;

    float c[2][2][4];
#pragma unroll
    for (int t = 0; t < 2; t++)
#pragma unroll
        for (int nt = 0; nt < 2; nt++)
#pragma unroll
            for (int j = 0; j < 4; j++) c[t][nt][j] = 0.f;

#pragma unroll 1
    for (int ch = 0; ch < 4; ch++) {
        __syncthreads();
#pragma unroll
        for (int it = 0; it < 4; it++) {
            int idx = it * 256 + tid;
            int row = idx >> 5, c4 = idx & 31;
            int grow = min(r0blk + row, NN - 1);
            float4 v = *(const float4*)(x + (size_t)grow * IC + ch * 128 + c4 * 4);
            uint4 u;
            u.x = tf32c(v.x); u.y = tf32c(v.y);
            u.z = tf32c(v.z); u.w = tf32c(v.w);
            *(uint4*)&xs[row * 132 + c4 * 4] = u;
        }
        __syncthreads();

#pragma unroll
        for (int kt2 = 0; kt2 < 16; kt2++) {
            int ktg = ch * 16 + kt2;
            uint a[2][4];
#pragma unroll
            for (int t = 0; t < 2; t++) {
                int r = t * 16 + q;
                a[t][0] = xs[r * 132 + kt2 * 8 + c2];
                a[t][1] = xs[(r + 8) * 132 + kt2 * 8 + c2];
                a[t][2] = xs[r * 132 + kt2 * 8 + c2 + 4];
                a[t][3] = xs[(r + 8) * 132 + kt2 * 8 + c2 + 4];
            }
#pragma unroll
            for (int nt = 0; nt < 2; nt++) {
                uint2 b = g_BpE[(ktg * 16 + warp * 2 + nt) * 32 + lane];
#pragma unroll
                for (int t = 0; t < 2; t++) mma_tf32(c[t][nt], a[t], b);
            }
        }
    }

#pragma unroll
    for (int t = 0; t < 2; t++) {
        int rowL = r0blk + t * 16 + q;
        int rowH = rowL + 8;
#pragma unroll
        for (int nt = 0; nt < 2; nt++) {
            int col = warp * 16 + nt * 8 + 2 * c2;
            if (rowL < NN)
                *(__nv_bfloat162*)&g_y[(size_t)rowL * OC + col] =
                    __float22bfloat162_rn(make_float2(c[t][nt][0], c[t][nt][1]));
            if (rowH < NN)
                *(__nv_bfloat162*)&g_y[(size_t)rowH * OC + col] =
                    __float22bfloat162_rn(make_float2(c[t][nt][2], c[t][nt][3]));
        }
    }
}

// ---------------------------------------------------------------------------
// K5: gather + epilogue, one warp per node, 8-wide software pipeline.
__device__ __forceinline__ float4 ld_y4(const uint2* y2, int row, int lane) {
    uint2 u = y2[(size_t)row * 32 + lane];
    float2 lo = __bfloat1622float2(*(__nv_bfloat162*)&u.x);
    float2 hi = __bfloat1622float2(*(__nv_bfloat162*)&u.y);
    return make_float4(lo.x, lo.y, hi.x, hi.y);
}

__global__ __launch_bounds__(256) void k_gather(const float* __restrict__ b) {
    const int w = blockIdx.x * 8 + (threadIdx.x >> 5);
    if (w >= NN) return;
    const int lane = threadIdx.x & 31;
    const int n = w;

    const uint2* __restrict__ y2 = (const uint2*)g_y;

    float dn = g_dis[n];
    float4 a = ld_y4(y2, n, lane);  // self loop
    a.x *= dn; a.y *= dn; a.z *= dn; a.w *= dn;

    int e = g_off[n], end = g_off[n + 1];
    for (; e + 8 <= end; e += 8) {
        int s[8];
#pragma unroll
        for (int j = 0; j < 8; j++) s[j] = g_csrc[e + j];
        float4 v[8];
#pragma unroll
        for (int j = 0; j < 8; j++) v[j] = ld_y4(y2, s[j], lane);
        float ds[8];
#pragma unroll
        for (int j = 0; j < 8; j++) ds[j] = g_dis[s[j]];
#pragma unroll
        for (int j = 0; j < 8; j++) {
            a.x = fmaf(v[j].x, ds[j], a.x);
            a.y = fmaf(v[j].y, ds[j], a.y);
            a.z = fmaf(v[j].z, ds[j], a.z);
            a.w = fmaf(v[j].w, ds[j], a.w);
        }
    }
    for (; e < end; e++) {
        int s = g_csrc[e];
        float ds = g_dis[s];
        float4 v = ld_y4(y2, s, lane);
        a.x = fmaf(v.x, ds, a.x); a.y = fmaf(v.y, ds, a.y);
        a.z = fmaf(v.z, ds, a.z); a.w = fmaf(v.w, ds, a.w);
    }
    const float4 b4 = ((const float4*)b)[lane];
    float4 h;
    h.x = fmaxf(fmaf(dn, a.x, b4.x), 0.f);
    h.y = fmaxf(fmaf(dn, a.y, b4.y), 0.f);
    h.z = fmaxf(fmaf(dn, a.z, b4.z), 0.f);
    h.w = fmaxf(fmaf(dn, a.w, b4.w), 0.f);
    ((float4*)g_h)[(size_t)n * 32 + lane] = h;
}

// ---------------------------------------------------------------------------
// K6: decode GEMM via tf32 mma.sync m16n8k8 + softmax.
// h staged in smem tf32-converted (uint) — no cvt in the mainloop.
__global__ __launch_bounds__(256) void k_dec(float* __restrict__ out) {
    __shared__ __align__(16) uint hs[32 * 132];
    __shared__ float red_m[2][16][8];
    __shared__ float red_s[2][16][8];
    const int tid = threadIdx.x, warp = tid >> 5, lane = tid & 31;
    const int q = lane >> 2, c2 = lane & 3;
    const int n0 = blockIdx.x * 32;

#pragma unroll
    for (int it = 0; it < 4; it++) {
        int idx = it * 256 + tid;
        int row = idx >> 5, c4 = idx & 31;
        float4 v = *(const float4*)(g_h + (size_t)(n0 + row) * OC + c4 * 4);
        uint4 u;
        u.x = tf32c(v.x); u.y = tf32c(v.y);
        u.z = tf32c(v.z); u.w = tf32c(v.w);
        *(uint4*)&hs[row * 132 + c4 * 4] = u;
    }
    __syncthreads();

    float c[2][8][4];
#pragma unroll
    for (int t = 0; t < 2; t++)
#pragma unroll
        for (int nt = 0; nt < 8; nt++)
#pragma unroll
            for (int j = 0; j < 4; j++) c[t][nt][j] = 0.f;

    for (int kt = 0; kt < 16; kt++) {
        uint a[2][4];
#pragma unroll
        for (int t = 0; t < 2; t++) {
            int r0 = t * 16 + q;
            a[t][0] = hs[r0 * 132 + kt * 8 + c2];
            a[t][1] = hs[(r0 + 8) * 132 + kt * 8 + c2];
            a[t][2] = hs[r0 * 132 + kt * 8 + c2 + 4];
            a[t][3] = hs[(r0 + 8) * 132 + kt * 8 + c2 + 4];
        }
#pragma unroll
        for (int nt = 0; nt < 8; nt++) {
            uint2 b = g_BpD[(kt * 64 + warp * 8 + nt) * 32 + lane];
#pragma unroll
            for (int t = 0; t < 2; t++) mma_tf32(c[t][nt], a[t], b);
        }
    }

    // --- softmax over 512 cols per row ---
#pragma unroll
    for (int t = 0; t < 2; t++) {
        float mL = -1e30f, mH = -1e30f;
#pragma unroll
        for (int nt = 0; nt < 8; nt++) {
            mL = fmaxf(mL, fmaxf(c[t][nt][0], c[t][nt][1]));
            mH = fmaxf(mH, fmaxf(c[t][nt][2], c[t][nt][3]));
        }
        mL = fmaxf(mL, __shfl_xor_sync(0xffffffffu, mL, 1));
        mL = fmaxf(mL, __shfl_xor_sync(0xffffffffu, mL, 2));
        mH = fmaxf(mH, __shfl_xor_sync(0xffffffffu, mH, 1));
        mH = fmaxf(mH, __shfl_xor_sync(0xffffffffu, mH, 2));
        if (c2 == 0) {
            red_m[t][q][warp] = mL;
            red_m[t][q + 8][warp] = mH;
        }
    }
    __syncthreads();

    float inv[2][2];
#pragma unroll
    for (int t = 0; t < 2; t++) {
        float rmL = red_m[t][q][0], rmH = red_m[t][q + 8][0];
#pragma unroll
        for (int w2 = 1; w2 < 8; w2++) {
            rmL = fmaxf(rmL, red_m[t][q][w2]);
            rmH = fmaxf(rmH, red_m[t][q + 8][w2]);
        }
        float sL = 0.f, sH = 0.f;
#pragma unroll
        for (int nt = 0; nt < 8; nt++) {
            c[t][nt][0] = __expf(c[t][nt][0] - rmL);
            c[t][nt][1] = __expf(c[t][nt][1] - rmL);
            c[t][nt][2] = __expf(c[t][nt][2] - rmH);
            c[t][nt][3] = __expf(c[t][nt][3] - rmH);
            sL += c[t][nt][0] + c[t][nt][1];
            sH += c[t][nt][2] + c[t][nt][3];
        }
        sL += __shfl_xor_sync(0xffffffffu, sL, 1);
        sL += __shfl_xor_sync(0xffffffffu, sL, 2);
        sH += __shfl_xor_sync(0xffffffffu, sH, 1);
        sH += __shfl_xor_sync(0xffffffffu, sH, 2);
        if (c2 == 0) {
            red_s[t][q][warp] = sL;
            red_s[t][q + 8][warp] = sH;
        }
    }
    __syncthreads();

#pragma unroll
    for (int t = 0; t < 2; t++) {
        float sL = 0.f, sH = 0.f;
#pragma unroll
        for (int w2 = 0; w2 < 8; w2++) {
            sL += red_s[t][q][w2];
            sH += red_s[t][q + 8][w2];
        }
        inv[t][0] = 1.f / sL;
        inv[t][1] = 1.f / sH;
    }

#pragma unroll
    for (int t = 0; t < 2; t++) {
        int rowL = n0 + t * 16 + q;
        int rowH = rowL + 8;
#pragma unroll
        for (int nt = 0; nt < 8; nt++) {
            int col = warp * 64 + nt * 8 + 2 * c2;
            if (rowL < NN) {
                float2 v = make_float2(c[t][nt][0] * inv[t][0],
                                       c[t][nt][1] * inv[t][0]);
                *(float2*)&out[(size_t)rowL * IC + col] = v;
            }
            if (rowH < NN) {
                float2 v = make_float2(c[t][nt][2] * inv[t][1],
                                       c[t][nt][3] * inv[t][1]);
                *(float2*)&out[(size_t)rowH * IC + col] = v;
            }
        }
    }
}

// ---------------------------------------------------------------------------
extern "C" void kernel_launch(void* const* d_in, const int* in_sizes, int n_in,
                              void* d_out, int out_size) {
    const float* x    = (const float*)d_in[0];
    const int*   ei   = (const int*)d_in[1];
    const float* Wenc = (const float*)d_in[2];
    const float* benc = (const float*)d_in[3];
    const float* Wdec = (const float*)d_in[4];
    float*       out  = (float*)d_out;

    // Streams/events created once on first (non-capture) call; reused.
    static cudaStream_t sB = nullptr;
    static cudaEvent_t evF = nullptr, evJ = nullptr;
    if (sB == nullptr) {
        cudaStreamCreateWithFlags(&sB, cudaStreamNonBlocking);
        cudaEventCreateWithFlags(&evF, cudaEventDisableTiming);
        cudaEventCreateWithFlags(&evJ, cudaEventDisableTiming);
    }

    // fork: stream B builds the CSR while the main stream runs the encode GEMM
    cudaEventRecord(evF, 0);
    cudaStreamWaitEvent(sB, evF, 0);

    k_deg<<<(NE + 255) / 256, 256, 0, sB>>>(ei);
    k_bsum<<<NB, 256, 0, sB>>>();
    k_off<<<NB, 256, 0, sB>>>();
    k_scatter<<<(NE + 255) / 256, 256, 0, sB>>>(ei);

    k_prep<<<128, 256>>>(Wenc, Wdec);
    k_gemm1<<<(NN + 31) / 32, 256>>>(x);

    // join
    cudaEventRecord(evJ, sB);
    cudaStreamWaitEvent(0, evJ, 0);

    k_gather<<<(NN + 7) / 8, 256>>>(benc);
    k_dec<<<(NN + 31) / 32, 256>>>(out);
}